// round 1
// baseline (speedup 1.0000x reference)
#include <cuda_runtime.h>

// SpatialLoss: per-segment variance loss over batch 0 only.
// inputs: superpixels_results int32 [2,1024,1024], feats float32 [2,64,1024,1024]
// output: scalar float32.

#define NSEG    2048
#define NCH     64
#define CG      8                 // channels per block (channel group)
#define NGROUPS (NCH / CG)        // 8
#define PIX     (1024 * 1024)
#define THREADS 256
#define CHUNK   28672             // pixels per block (28 iters of 1024)
#define NPX     ((PIX + CHUNK - 1) / CHUNK)   // 37  -> 37*8 = 296 blocks = 148 SMs * 2

__device__ float g_sum[NSEG * NCH];   // [seg][ch]
__device__ float g_ssq[NSEG];         // sum over all channels of x^2, per segment
__device__ float g_cnt[NSEG];         // pixel count per segment

__global__ void zero_kernel() {
    int i = blockIdx.x * blockDim.x + threadIdx.x;
    if (i < NSEG * NCH) g_sum[i] = 0.0f;
    else if (i < NSEG * NCH + NSEG) g_ssq[i - NSEG * NCH] = 0.0f;
    else if (i < NSEG * NCH + 2 * NSEG) g_cnt[i - NSEG * NCH - NSEG] = 0.0f;
}

__global__ __launch_bounds__(THREADS, 2)
void accum_kernel(const int* __restrict__ sp, const float* __restrict__ feats) {
    // dynamic smem: s_sum[CG][NSEG] | s_ssq[NSEG] | s_cnt[NSEG]  = 10*2048 floats = 80KB
    extern __shared__ float smem[];
    float* s_sum = smem;                 // [CG][NSEG]  (ch-major so seg spreads banks)
    float* s_ssq = smem + CG * NSEG;     // [NSEG]
    float* s_cnt = s_ssq + NSEG;         // [NSEG]

    const int tid = threadIdx.x;
    const int cg  = blockIdx.y;

    for (int i = tid; i < (CG + 2) * NSEG; i += THREADS) smem[i] = 0.0f;
    __syncthreads();

    const int base  = blockIdx.x * CHUNK;
    const int iters = CHUNK / (THREADS * 4);   // 28

    for (int it = 0; it < iters; it++) {
        const int p = base + (it * THREADS + tid) * 4;
        if (p < PIX) {
            const int4 s4 = *(const int4*)(sp + p);
            float q0 = 0.f, q1 = 0.f, q2 = 0.f, q3 = 0.f;
            #pragma unroll
            for (int ci = 0; ci < CG; ci++) {
                const float4 v = *(const float4*)(feats + (size_t)(cg * CG + ci) * PIX + p);
                atomicAdd(&s_sum[ci * NSEG + s4.x], v.x); q0 += v.x * v.x;
                atomicAdd(&s_sum[ci * NSEG + s4.y], v.y); q1 += v.y * v.y;
                atomicAdd(&s_sum[ci * NSEG + s4.z], v.z); q2 += v.z * v.z;
                atomicAdd(&s_sum[ci * NSEG + s4.w], v.w); q3 += v.w * v.w;
            }
            atomicAdd(&s_ssq[s4.x], q0);
            atomicAdd(&s_ssq[s4.y], q1);
            atomicAdd(&s_ssq[s4.z], q2);
            atomicAdd(&s_ssq[s4.w], q3);
            if (cg == 0) {
                atomicAdd(&s_cnt[s4.x], 1.0f);
                atomicAdd(&s_cnt[s4.y], 1.0f);
                atomicAdd(&s_cnt[s4.z], 1.0f);
                atomicAdd(&s_cnt[s4.w], 1.0f);
            }
        }
    }
    __syncthreads();

    // flush privatized accumulators to global
    for (int i = tid; i < CG * NSEG; i += THREADS) {
        const int ci = i >> 11;           // i / NSEG
        const int seg = i & (NSEG - 1);   // i % NSEG
        const float v = s_sum[i];
        if (v != 0.0f) atomicAdd(&g_sum[seg * NCH + cg * CG + ci], v);
    }
    for (int seg = tid; seg < NSEG; seg += THREADS) {
        const float v = s_ssq[seg];
        if (v != 0.0f) atomicAdd(&g_ssq[seg], v);
        if (cg == 0) {
            const float cc = s_cnt[seg];
            if (cc != 0.0f) atomicAdd(&g_cnt[seg], cc);
        }
    }
}

__global__ void finalize_kernel(float* __restrict__ out) {
    __shared__ float red_loss[1024];
    __shared__ float red_cnt[1024];
    const int tid = threadIdx.x;
    float loss = 0.0f, nz = 0.0f;
    for (int seg = tid; seg < NSEG; seg += 1024) {
        const float n   = g_cnt[seg];
        const float ssq = g_ssq[seg];
        float s2 = 0.0f;
        #pragma unroll
        for (int c = 0; c < NCH; c++) {
            const float s = g_sum[seg * NCH + c];
            s2 += s * s;
        }
        const float nn = fmaxf(n, 1.0f);
        const float var_sum = ssq - s2 / nn;
        const float per_seg = var_sum / ((float)NCH * nn);
        if (n >= 2.0f) loss += per_seg;
        if (n > 0.0f)  nz += 1.0f;
    }
    red_loss[tid] = loss;
    red_cnt[tid]  = nz;
    __syncthreads();
    for (int s = 512; s > 0; s >>= 1) {
        if (tid < s) {
            red_loss[tid] += red_loss[tid + s];
            red_cnt[tid]  += red_cnt[tid + s];
        }
        __syncthreads();
    }
    if (tid == 0) out[0] = red_loss[0] / red_cnt[0];
}

extern "C" void kernel_launch(void* const* d_in, const int* in_sizes, int n_in,
                              void* d_out, int out_size) {
    // Detect input order by size: sp has 2*1024*1024 ints, feats 2*64*1024*1024 floats.
    const int* sp;
    const float* feats;
    if (in_sizes[0] == 2 * 1024 * 1024) {
        sp    = (const int*)d_in[0];
        feats = (const float*)d_in[1];
    } else {
        sp    = (const int*)d_in[1];
        feats = (const float*)d_in[0];
    }

    const int smem_bytes = (CG + 2) * NSEG * (int)sizeof(float);  // 81920
    cudaFuncSetAttribute(accum_kernel,
                         cudaFuncAttributeMaxDynamicSharedMemorySize, smem_bytes);

    const int zero_total = NSEG * NCH + 2 * NSEG;
    zero_kernel<<<(zero_total + 255) / 256, 256>>>();

    dim3 grid(NPX, NGROUPS);
    accum_kernel<<<grid, THREADS, smem_bytes>>>(sp, feats);

    finalize_kernel<<<1, 1024>>>((float*)d_out);
}

// round 2
// speedup vs baseline: 1.6435x; 1.6435x over previous
#include <cuda_runtime.h>

// SpatialLoss: per-segment variance loss over batch 0 only.
// inputs: superpixels_results int32 [2,1024,1024], feats float32 [2,64,1024,1024]
// output: scalar float32.
//
// Strategy: all per-(seg,ch) accumulation goes through L2 vector atomics
// (red.global.add.v4.f32), which run on 192 LTS partitions in parallel,
// instead of SM shared-memory atomics (1 lane/cyc/SM -> was the 268us wall).

#define NSEG    2048
#define NCH     64
#define PIX     (1024 * 1024)
#define THREADS 256

__device__ float  g_sum[NSEG * NCH];   // [seg][ch]
__device__ float2 g_sc[NSEG];          // (sum over channels of x^2, pixel count)

__device__ __forceinline__ void red4(float* p, float a, float b, float c, float d) {
    asm volatile("red.global.add.v4.f32 [%0], {%1, %2, %3, %4};"
                 :: "l"(p), "f"(a), "f"(b), "f"(c), "f"(d) : "memory");
}
__device__ __forceinline__ void red2(float2* p, float a, float b) {
    asm volatile("red.global.add.v2.f32 [%0], {%1, %2};"
                 :: "l"(p), "f"(a), "f"(b) : "memory");
}

__global__ void zero_kernel() {
    int i = blockIdx.x * blockDim.x + threadIdx.x;
    if (i < NSEG * NCH) g_sum[i] = 0.0f;
    int j = i - NSEG * NCH;
    if (j >= 0 && j < NSEG) g_sc[j] = make_float2(0.0f, 0.0f);
}

__global__ __launch_bounds__(THREADS)
void accum_kernel(const int* __restrict__ sp, const float* __restrict__ feats) {
    // one thread owns 4 consecutive pixels, all 64 channels
    const int t = blockIdx.x * THREADS + threadIdx.x;
    const int p = t * 4;
    if (p >= PIX) return;

    const int4 s4 = *(const int4*)(sp + p);
    float* d0 = &g_sum[s4.x * NCH];
    float* d1 = &g_sum[s4.y * NCH];
    float* d2 = &g_sum[s4.z * NCH];
    float* d3 = &g_sum[s4.w * NCH];

    float q0 = 0.f, q1 = 0.f, q2 = 0.f, q3 = 0.f;

    #pragma unroll
    for (int cq = 0; cq < NCH / 4; cq++) {
        // load 4 channels x 4 pixels (each float4 = one channel, 4 pixels)
        const float4 a = *(const float4*)(feats + (size_t)(cq * 4 + 0) * PIX + p);
        const float4 b = *(const float4*)(feats + (size_t)(cq * 4 + 1) * PIX + p);
        const float4 c = *(const float4*)(feats + (size_t)(cq * 4 + 2) * PIX + p);
        const float4 e = *(const float4*)(feats + (size_t)(cq * 4 + 3) * PIX + p);

        // transpose in registers: per-pixel channel quads -> one 16B L2 atomic each
        red4(d0 + cq * 4, a.x, b.x, c.x, e.x);
        red4(d1 + cq * 4, a.y, b.y, c.y, e.y);
        red4(d2 + cq * 4, a.z, b.z, c.z, e.z);
        red4(d3 + cq * 4, a.w, b.w, c.w, e.w);

        q0 += a.x * a.x + b.x * b.x + c.x * c.x + e.x * e.x;
        q1 += a.y * a.y + b.y * b.y + c.y * c.y + e.y * e.y;
        q2 += a.z * a.z + b.z * b.z + c.z * c.z + e.z * e.z;
        q3 += a.w * a.w + b.w * b.w + c.w * c.w + e.w * e.w;
    }

    red2(&g_sc[s4.x], q0, 1.0f);
    red2(&g_sc[s4.y], q1, 1.0f);
    red2(&g_sc[s4.z], q2, 1.0f);
    red2(&g_sc[s4.w], q3, 1.0f);
}

__global__ void finalize_kernel(float* __restrict__ out) {
    __shared__ float red_loss[1024];
    __shared__ float red_cnt[1024];
    const int tid = threadIdx.x;
    float loss = 0.0f, nz = 0.0f;
    for (int seg = tid; seg < NSEG; seg += 1024) {
        const float2 sc = g_sc[seg];
        const float n   = sc.y;
        const float ssq = sc.x;
        float s2 = 0.0f;
        #pragma unroll
        for (int c = 0; c < NCH; c += 4) {
            const float4 s = *(const float4*)&g_sum[seg * NCH + c];
            s2 += s.x * s.x + s.y * s.y + s.z * s.z + s.w * s.w;
        }
        const float nn = fmaxf(n, 1.0f);
        const float var_sum = ssq - s2 / nn;
        const float per_seg = var_sum / ((float)NCH * nn);
        if (n >= 2.0f) loss += per_seg;
        if (n > 0.0f)  nz += 1.0f;
    }
    red_loss[tid] = loss;
    red_cnt[tid]  = nz;
    __syncthreads();
    for (int s = 512; s > 0; s >>= 1) {
        if (tid < s) {
            red_loss[tid] += red_loss[tid + s];
            red_cnt[tid]  += red_cnt[tid + s];
        }
        __syncthreads();
    }
    if (tid == 0) out[0] = red_loss[0] / red_cnt[0];
}

extern "C" void kernel_launch(void* const* d_in, const int* in_sizes, int n_in,
                              void* d_out, int out_size) {
    const int* sp;
    const float* feats;
    if (in_sizes[0] == 2 * 1024 * 1024) {
        sp    = (const int*)d_in[0];
        feats = (const float*)d_in[1];
    } else {
        sp    = (const int*)d_in[1];
        feats = (const float*)d_in[0];
    }

    const int zero_total = NSEG * NCH + NSEG;          // float slots + float2 slots
    zero_kernel<<<(zero_total + 255) / 256, 256>>>();

    const int nthreads_total = PIX / 4;                 // 262144
    accum_kernel<<<nthreads_total / THREADS, THREADS>>>(sp, feats);

    finalize_kernel<<<1, 1024>>>((float*)d_out);
}